// round 13
// baseline (speedup 1.0000x reference)
#include <cuda_runtime.h>
#include <cuda_bf16.h>

#define N_PTS 16384
#define KNN   16
#define NBINS 1024
#define QBLK  64
#define NTILE (N_PTS / QBLK)
#define BINW  (12.0f / NBINS)

__device__ int    g_nbr[N_PTS * KNN];
__device__ float  g_h0[N_PTS * 6];
__device__ float4 g_ps[N_PTS];     // bin-ordered points (x,y,z,|p|^2)
__device__ int    g_sidx[N_PTS];   // original index per scattered slot
__device__ int    g_hist[NBINS];
__device__ int    g_off[NBINS];
__device__ int    g_cur[NBINS];

// ---------------- packed f32x2 helpers (convs) ----------------
__device__ __forceinline__ unsigned long long pk2(float lo, float hi) {
    unsigned long long r;
    asm("mov.b64 %0, {%1, %2};" : "=l"(r) : "f"(lo), "f"(hi));
    return r;
}
__device__ __forceinline__ void upk2(unsigned long long v, float& lo, float& hi) {
    asm("mov.b64 {%0, %1}, %2;" : "=f"(lo), "=f"(hi) : "l"(v));
}
__device__ __forceinline__ void fma2(unsigned long long& d, unsigned long long a,
                                     unsigned long long b) {
    asm("fma.rn.f32x2 %0, %1, %2, %0;" : "+l"(d) : "l"(a), "l"(b));
}
__device__ __forceinline__ unsigned long long add2(unsigned long long a,
                                                   unsigned long long b) {
    unsigned long long d;
    asm("add.rn.f32x2 %0, %1, %2;" : "=l"(d) : "l"(a), "l"(b));
    return d;
}
__device__ __forceinline__ unsigned long long mul2(unsigned long long a,
                                                   unsigned long long b) {
    unsigned long long d;
    asm("mul.rn.f32x2 %0, %1, %2;" : "=l"(d) : "l"(a), "l"(b));
    return d;
}

__device__ __forceinline__ int bin_of(float x) {
    int b = (int)((x + 6.0f) * ((float)NBINS / 12.0f));
    return min(max(b, 0), NBINS - 1);
}

// ---------------------------------------------------------------------------
__global__ void hist_kernel(const float* __restrict__ pos)
{
    const int i = blockIdx.x * 256 + threadIdx.x;
    if (i < N_PTS) atomicAdd(&g_hist[bin_of(pos[3 * i])], 1);
}

__global__ void scan_kernel()
{
    __shared__ int s[NBINS];
    const int t = threadIdx.x;
    const int v = g_hist[t];
    s[t] = v;
    __syncthreads();
    for (int d = 1; d < NBINS; d <<= 1) {
        const int a = (t >= d) ? s[t - d] : 0;
        __syncthreads();
        s[t] += a;
        __syncthreads();
    }
    g_off[t] = s[t] - v;   // exclusive prefix
}

__global__ void scatter_kernel(const float* __restrict__ pos)
{
    const int i = blockIdx.x * 256 + threadIdx.x;
    if (i < N_PTS) {
        const float x = pos[3 * i], y = pos[3 * i + 1], z = pos[3 * i + 2];
        const int b = bin_of(x);
        const int p = g_off[b] + atomicAdd(&g_cur[b], 1);
        g_ps[p] = make_float4(x, y, z, fmaf(x, x, fmaf(y, y, z * z)));
        g_sidx[p] = i;
    }
}

// ---------------------------------------------------------------------------
// kNN: sorted-window sweep. Exact d2 (bit-identical to the passing build),
// exact (d2, idx) ordering via u64 keys, conservative tile pruning.
// ---------------------------------------------------------------------------
__device__ __forceinline__ void ins64(unsigned long long k,
                                      unsigned long long (&ks)[KNN])
{
#pragma unroll
    for (int r = KNN - 1; r >= 1; r--) {
        const bool keep  = ks[r] <= k;
        const bool shift = ks[r - 1] > k;
        ks[r] = keep ? ks[r] : (shift ? ks[r - 1] : k);
    }
    ks[0] = (ks[0] <= k) ? ks[0] : k;
}

__device__ __forceinline__ float key_to_d2(unsigned long long k)
{
    unsigned int u = (unsigned int)(k >> 32);
    u = (u & 0x80000000u) ? (u ^ 0x80000000u) : ~u;
    return __uint_as_float(u);
}

__device__ __forceinline__ void knn_tile(
    int t, const float4& q,
    unsigned long long (&keys)[KNN], float& thr,
    float4* tile, int* tidx, float* wmin, float* wmax, int tid,
    float& txmin, float& txmax)
{
    __syncthreads();   // previous tile fully consumed
    const float4 c = g_ps[t * QBLK + tid];
    tile[tid] = c;
    tidx[tid] = g_sidx[t * QBLK + tid];
    float mn = c.x, mx = c.x;
#pragma unroll
    for (int off = 16; off >= 1; off >>= 1) {
        mn = fminf(mn, __shfl_xor_sync(0xffffffffu, mn, off));
        mx = fmaxf(mx, __shfl_xor_sync(0xffffffffu, mx, off));
    }
    if ((tid & 31) == 0) { wmin[tid >> 5] = mn; wmax[tid >> 5] = mx; }
    __syncthreads();
    txmin = fminf(wmin[0], wmin[1]);
    txmax = fmaxf(wmax[0], wmax[1]);

    const float dx = fmaxf(fmaxf(txmin - q.x, q.x - txmax), 0.f);
    if (dx * dx <= thr + 2e-4f) {
#pragma unroll 4
        for (int j = 0; j < QBLK; j++) {
            const float4 cc = tile[j];
            float dot = q.x * cc.x;
            dot = fmaf(q.y, cc.y, dot);
            dot = fmaf(q.z, cc.z, dot);
            const float d2 = fmaf(-2.0f, dot, q.w + cc.w);
            if (d2 <= thr) {
                unsigned int s = __float_as_uint(d2);
                s ^= (s & 0x80000000u) ? 0xFFFFFFFFu : 0x80000000u;
                const unsigned long long k =
                    ((unsigned long long)s << 32) | (unsigned int)tidx[j];
                if (k < keys[KNN - 1]) {
                    ins64(k, keys);
                    thr = key_to_d2(keys[KNN - 1]);
                }
            }
        }
    }
}

__global__ void __launch_bounds__(QBLK) knn_kernel(int* __restrict__ nbr)
{
    __shared__ float4 tile[QBLK];
    __shared__ int    tidx[QBLK];
    __shared__ float  wmin[2], wmax[2];

    const int tid = threadIdx.x;
    const int B   = blockIdx.x;
    const float4 q = g_ps[B * QBLK + tid];
    const int qorig = g_sidx[B * QBLK + tid];

    unsigned long long keys[KNN];
#pragma unroll
    for (int r = 0; r < KNN; r++) keys[r] = 0xFF800000FFFFFFFFull;  // +inf key
    float thr = __uint_as_float(0x7F800000u);                        // +inf

    float txmin, txmax;

    // right sweep (includes own tile)
    int stop = 0;
    for (int t = B; t < NTILE && !stop; t++) {
        knn_tile(t, q, keys, thr, tile, tidx, wmin, wmax, tid, txmin, txmax);
        const float g = (txmax - BINW) - q.x;
        const int pr = (g > 0.f) && (g * g > thr + 2e-4f);
        stop = __syncthreads_and(pr);
    }
    // left sweep
    stop = 0;
    for (int t = B - 1; t >= 0 && !stop; t--) {
        knn_tile(t, q, keys, thr, tile, tidx, wmin, wmax, tid, txmin, txmax);
        const float g = q.x - (txmin + BINW);
        const int pr = (g > 0.f) && (g * g > thr + 2e-4f);
        stop = __syncthreads_and(pr);
    }

#pragma unroll
    for (int r = 0; r < KNN; r++)
        nbr[qorig * KNN + r] = (int)(unsigned int)(keys[r] & 0xFFFFFFFFu);
}

// ---------------------------------------------------------------------------
__global__ void concat_kernel(const float* __restrict__ pos,
                              const float* __restrict__ normal,
                              float* __restrict__ h0)
{
    const int i = blockIdx.x * 256 + threadIdx.x;
    if (i < N_PTS) {
#pragma unroll
        for (int c = 0; c < 3; c++) {
            h0[i * 6 + c]     = pos[i * 3 + c];
            h0[i * 6 + 3 + c] = normal[i * 3 + c];
        }
    }
}

// ---------------------------------------------------------------------------
// SMEM-tiled fused PointNetConv (exact fp32; unchanged from passing R11).
// ---------------------------------------------------------------------------
template <int CIN_X, int C1, int C2>
__global__ void __launch_bounds__(256) conv_kernel(
    const float* __restrict__ x, const float* __restrict__ pos,
    const int* __restrict__ nbr,
    const float* __restrict__ Wa, const float* __restrict__ ba,
    const float* __restrict__ gmm, const float* __restrict__ bet,
    const float* __restrict__ Wb, const float* __restrict__ bb,
    float* __restrict__ out)
{
    constexpr int CIN = CIN_X + 3;
    constexpr int EP  = 260;
    constexpr int NC  = C1 / 8;
    constexpr int NG  = NC / 8;
    constexpr int R0F = (CIN * EP + CIN * C1 > C1 * EP) ? (CIN * EP + CIN * C1)
                                                        : (C1 * EP);

    extern __shared__ float smf[];
    float* sM  = smf;
    float* sWa = smf + CIN * EP;
    float* sH  = smf;
    float* sWb = smf + R0F;
    float* sba = sWb + C1 * C2;
    float* sg  = sba + C1;
    float* sbe = sg + C1;
    float* sbb = sbe + C1;

    const int tid = threadIdx.x;
    const int eo  = tid >> 3;
    const int co  = tid & 7;

    for (int i = tid; i < CIN * C1; i += 256) sWa[i] = Wa[i];
    for (int i = tid; i < C1 * C2; i += 256) sWb[i] = Wb[i];
    if (tid < C1) { sba[tid] = ba[tid]; sg[tid] = gmm[tid]; sbe[tid] = bet[tid]; }
    if (tid < C2) sbb[tid] = bb[tid];

    {
        const int e    = tid;
        const int node = (blockIdx.x << 4) + (e >> 4);
        const int j    = nbr[(node << 4) + (e & 15)];
        if constexpr (CIN_X == 6) {
            const float2* xj2 = (const float2*)(x + (long)j * 6);
#pragma unroll
            for (int p = 0; p < 3; p++) {
                const float2 v = __ldg(xj2 + p);
                sM[(2 * p) * EP + e]     = v.x;
                sM[(2 * p + 1) * EP + e] = v.y;
            }
        } else {
            const float4* xj4 = (const float4*)(x + (long)j * CIN_X);
#pragma unroll
            for (int p = 0; p < CIN_X / 4; p++) {
                const float4 v = __ldg(xj4 + p);
                sM[(4 * p) * EP + e]     = v.x;
                sM[(4 * p + 1) * EP + e] = v.y;
                sM[(4 * p + 2) * EP + e] = v.z;
                sM[(4 * p + 3) * EP + e] = v.w;
            }
        }
        sM[(CIN_X + 0) * EP + e] = pos[3 * j]     - pos[3 * node];
        sM[(CIN_X + 1) * EP + e] = pos[3 * j + 1] - pos[3 * node + 1];
        sM[(CIN_X + 2) * EP + e] = pos[3 * j + 2] - pos[3 * node + 2];
    }
    __syncthreads();

    unsigned long long acc[NC][4];
#pragma unroll
    for (int c = 0; c < NC; c++) {
        const float b = sba[co * NC + c];
        const unsigned long long bd = pk2(b, b);
#pragma unroll
        for (int ep = 0; ep < 4; ep++) acc[c][ep] = bd;
    }
#pragma unroll 2
    for (int k = 0; k < CIN; k++) {
        const ulonglong2 mv0 = *(const ulonglong2*)(sM + k * EP + 8 * eo);
        const ulonglong2 mv1 = *(const ulonglong2*)(sM + k * EP + 8 * eo + 4);
        float wv[NC];
#pragma unroll
        for (int q4 = 0; q4 < NC / 4; q4++) {
            const float4 t = *(const float4*)(sWa + k * C1 + co * NC + 4 * q4);
            wv[4 * q4] = t.x; wv[4 * q4 + 1] = t.y;
            wv[4 * q4 + 2] = t.z; wv[4 * q4 + 3] = t.w;
        }
#pragma unroll
        for (int c = 0; c < NC; c++) {
            const unsigned long long wd = pk2(wv[c], wv[c]);
            fma2(acc[c][0], mv0.x, wd);
            fma2(acc[c][1], mv0.y, wd);
            fma2(acc[c][2], mv1.x, wd);
            fma2(acc[c][3], mv1.y, wd);
        }
    }
    __syncthreads();

#pragma unroll
    for (int gi = 0; gi < NG; gi++) {
        const int cb = gi * 8;
#pragma unroll
        for (int ep = 0; ep < 4; ep++) {
            unsigned long long ssum = acc[cb][ep];
            unsigned long long qq = mul2(acc[cb][ep], acc[cb][ep]);
#pragma unroll
            for (int c = 1; c < 8; c++) {
                ssum = add2(ssum, acc[cb + c][ep]);
                fma2(qq, acc[cb + c][ep], acc[cb + c][ep]);
            }
            float s0, s1, q0, q1;
            upk2(ssum, s0, s1);
            upk2(qq, q0, q1);
            const float mu0 = s0 * 0.125f, mu1 = s1 * 0.125f;
            const float rs0 = rsqrtf(fmaf(-mu0, mu0, q0 * 0.125f) + 1e-5f);
            const float rs1 = rsqrtf(fmaf(-mu1, mu1, q1 * 0.125f) + 1e-5f);
#pragma unroll
            for (int c = 0; c < 8; c++) {
                const int gc = co * NC + cb + c;
                const float gam = sg[gc], bet_ = sbe[gc];
                float v0, v1;
                upk2(acc[cb + c][ep], v0, v1);
                v0 = fmaxf(fmaf((v0 - mu0) * rs0, gam, bet_), 0.f);
                v1 = fmaxf(fmaf((v1 - mu1) * rs1, gam, bet_), 0.f);
                *(float2*)(sH + gc * EP + 8 * eo + 2 * ep) = make_float2(v0, v1);
            }
        }
    }
    __syncthreads();

    unsigned long long a2[NC][4];
#pragma unroll
    for (int c = 0; c < NC; c++) {
        const float b = sbb[co * NC + c];
        const unsigned long long bd = pk2(b, b);
#pragma unroll
        for (int ep = 0; ep < 4; ep++) a2[c][ep] = bd;
    }
#pragma unroll 2
    for (int k = 0; k < C1; k++) {
        const ulonglong2 hv0 = *(const ulonglong2*)(sH + k * EP + 8 * eo);
        const ulonglong2 hv1 = *(const ulonglong2*)(sH + k * EP + 8 * eo + 4);
        float wv[NC];
#pragma unroll
        for (int q4 = 0; q4 < NC / 4; q4++) {
            const float4 t = *(const float4*)(sWb + k * C2 + co * NC + 4 * q4);
            wv[4 * q4] = t.x; wv[4 * q4 + 1] = t.y;
            wv[4 * q4 + 2] = t.z; wv[4 * q4 + 3] = t.w;
        }
#pragma unroll
        for (int c = 0; c < NC; c++) {
            const unsigned long long wd = pk2(wv[c], wv[c]);
            fma2(a2[c][0], hv0.x, wd);
            fma2(a2[c][1], hv0.y, wd);
            fma2(a2[c][2], hv1.x, wd);
            fma2(a2[c][3], hv1.y, wd);
        }
    }

    float vmax[NC];
#pragma unroll
    for (int c = 0; c < NC; c++) {
        float m0, m1, t0, t1;
        upk2(a2[c][0], m0, m1);
        m0 = fmaxf(m0, m1);
        upk2(a2[c][1], t0, t1);
        m0 = fmaxf(m0, fmaxf(t0, t1));
        upk2(a2[c][2], t0, t1);
        m0 = fmaxf(m0, fmaxf(t0, t1));
        upk2(a2[c][3], t0, t1);
        m0 = fmaxf(m0, fmaxf(t0, t1));
        vmax[c] = m0;
    }
#pragma unroll
    for (int c = 0; c < NC; c++)
        vmax[c] = fmaxf(vmax[c], __shfl_xor_sync(0xffffffffu, vmax[c], 8));

    if (!(eo & 1)) {
        const int node = (blockIdx.x << 4) + (eo >> 1);
        float* op = out + (long)node * C2 + co * NC;
#pragma unroll
        for (int q4 = 0; q4 < NC / 4; q4++) {
            *(float4*)(op + 4 * q4) = make_float4(
                fmaxf(vmax[4 * q4], 0.f),     fmaxf(vmax[4 * q4 + 1], 0.f),
                fmaxf(vmax[4 * q4 + 2], 0.f), fmaxf(vmax[4 * q4 + 3], 0.f));
        }
    }
}

// ---------------------------------------------------------------------------
template <int CIN_X, int C1, int C2>
static int conv_smem_bytes()
{
    constexpr int CIN = CIN_X + 3;
    constexpr int EP  = 260;
    constexpr int R0F = (CIN * EP + CIN * C1 > C1 * EP) ? (CIN * EP + CIN * C1)
                                                        : (C1 * EP);
    return (R0F + C1 * C2 + 3 * C1 + C2) * 4;
}

extern "C" void kernel_launch(void* const* d_in, const int* in_sizes, int n_in,
                              void* d_out, int out_size)
{
    const float* pos    = (const float*)d_in[0];
    const float* normal = (const float*)d_in[1];
    const float* W1a = (const float*)d_in[2];
    const float* b1a = (const float*)d_in[3];
    const float* g1  = (const float*)d_in[4];
    const float* be1 = (const float*)d_in[5];
    const float* W1b = (const float*)d_in[6];
    const float* b1b = (const float*)d_in[7];
    const float* W2a = (const float*)d_in[8];
    const float* b2a = (const float*)d_in[9];
    const float* g2  = (const float*)d_in[10];
    const float* be2 = (const float*)d_in[11];
    const float* W2b = (const float*)d_in[12];
    const float* b2b = (const float*)d_in[13];
    const float* W3a = (const float*)d_in[14];
    const float* b3a = (const float*)d_in[15];
    const float* g3  = (const float*)d_in[16];
    const float* be3 = (const float*)d_in[17];
    const float* W3b = (const float*)d_in[18];
    const float* b3b = (const float*)d_in[19];

    float* out = (float*)d_out;
    float* h1 = out;
    float* h2 = out + (size_t)N_PTS * 64;
    float* h3 = out + (size_t)N_PTS * 128;

    void *nbr_p = nullptr, *h0_p = nullptr, *hist_p = nullptr, *cur_p = nullptr;
    cudaGetSymbolAddress(&nbr_p, g_nbr);
    cudaGetSymbolAddress(&h0_p, g_h0);
    cudaGetSymbolAddress(&hist_p, g_hist);
    cudaGetSymbolAddress(&cur_p, g_cur);
    int*   nbr = (int*)nbr_p;
    float* h0  = (float*)h0_p;

    const int sm1 = conv_smem_bytes<6, 64, 64>();
    const int sm2 = conv_smem_bytes<64, 64, 64>();
    const int sm3 = conv_smem_bytes<64, 128, 128>();

    cudaFuncSetAttribute(conv_kernel<6, 64, 64>,
                         cudaFuncAttributeMaxDynamicSharedMemorySize, sm1);
    cudaFuncSetAttribute(conv_kernel<64, 64, 64>,
                         cudaFuncAttributeMaxDynamicSharedMemorySize, sm2);
    cudaFuncSetAttribute(conv_kernel<64, 128, 128>,
                         cudaFuncAttributeMaxDynamicSharedMemorySize, sm3);

    cudaMemsetAsync(hist_p, 0, NBINS * sizeof(int));
    cudaMemsetAsync(cur_p, 0, NBINS * sizeof(int));

    hist_kernel<<<N_PTS / 256, 256>>>(pos);
    scan_kernel<<<1, NBINS>>>();
    scatter_kernel<<<N_PTS / 256, 256>>>(pos);
    knn_kernel<<<NTILE, QBLK>>>(nbr);
    concat_kernel<<<N_PTS / 256, 256>>>(pos, normal, h0);

    conv_kernel<6, 64, 64><<<N_PTS / 16, 256, sm1>>>(
        h0, pos, nbr, W1a, b1a, g1, be1, W1b, b1b, h1);
    conv_kernel<64, 64, 64><<<N_PTS / 16, 256, sm2>>>(
        h1, pos, nbr, W2a, b2a, g2, be2, W2b, b2b, h2);
    conv_kernel<64, 128, 128><<<N_PTS / 16, 256, sm3>>>(
        h2, pos, nbr, W3a, b3a, g3, be3, W3b, b3b, h3);
}